// round 4
// baseline (speedup 1.0000x reference)
#include <cuda_runtime.h>
#include <cuda_bf16.h>

// ---------------------------------------------------------------------------
// SchNet interaction block, GB300 sm_103a — FFMA2 (fma.rn.f32x2) pipeline v3.
//   K1: XF = x @ W_in2f                                   (gemm32)
//   K2: per-atom fused filter MLP + gather + aggregate    (fused_filter)
//   K3: out = ssp((Y@W_f2out+b_f2out)@W_dense + G@W_ang + b_dense)  (tail)
// v3: flat unrolled MMA body (no dynamic trip counts), double-buffered
//     weight staging, float4 A-operand loads, fused tail.
// ---------------------------------------------------------------------------

#define BDIM 256
#define NB   64
#define KS   128
#define NF   256
#define NATOMS 4096
#define CUTOFF 5.0f

__device__ float g_XF[NATOMS * NF];
__device__ float g_Y [NATOMS * NF];

// ---- packed f32x2 helpers --------------------------------------------------

__device__ __forceinline__ void fma2(unsigned long long& d,
                                     unsigned long long a,
                                     unsigned long long b) {
    asm("fma.rn.f32x2 %0, %1, %2, %3;" : "=l"(d) : "l"(a), "l"(b), "l"(d));
}
__device__ __forceinline__ unsigned long long pack_dup(float v) {
    unsigned long long r;
    asm("mov.b64 %0, {%1, %1};" : "=l"(r) : "f"(v));
    return r;
}
__device__ __forceinline__ float2 unpack2(unsigned long long u) {
    float2 r;
    asm("mov.b64 {%0, %1}, %2;" : "=f"(r.x), "=f"(r.y) : "l"(u));
    return r;
}
__device__ __forceinline__ float f4c(const float4& v, int i) {
    return i == 0 ? v.x : i == 1 ? v.y : i == 2 ? v.z : v.w;
}
__device__ __forceinline__ float sspf(float v) {
    float e = __expf(v);
    float r = __logf(fmaf(0.5f, e, 0.5f));
    return (v > 60.0f) ? (v - 0.69314718055994531f) : r;
}

// ---- shared 8-deep MMA tile: acc[j][*] += A[rowbase+j, 0..7] * Wtile -------
// cur: staged 8x256 weight tile.  sA: A rows (lda floats), pre-offset by k0.

template<int JROWS>
__device__ __forceinline__ void mma_tile8(const float* cur, const float* sA,
                                          int lda, int rowbase, int f0,
                                          unsigned long long (&acc)[JROWS][4])
{
    #pragma unroll
    for (int kq = 0; kq < 8; kq += 4) {
        float4 av[JROWS];
        #pragma unroll
        for (int j = 0; j < JROWS; ++j)
            av[j] = *(const float4*)&sA[(rowbase + j) * lda + kq];
        #pragma unroll
        for (int kk = 0; kk < 4; ++kk) {
            ulonglong2 bva = *(const ulonglong2*)&cur[(kq + kk) * 256 + f0];
            ulonglong2 bvb = *(const ulonglong2*)&cur[(kq + kk) * 256 + f0 + 4];
            #pragma unroll
            for (int j = 0; j < JROWS; ++j) {
                unsigned long long a2 = pack_dup(f4c(av[j], kk));
                fma2(acc[j][0], a2, bva.x);
                fma2(acc[j][1], a2, bva.y);
                fma2(acc[j][2], a2, bvb.x);
                fma2(acc[j][3], a2, bvb.y);
            }
        }
    }
}

// ---- K1: 32-row GEMM, C = A @ W  (K=256, N=256) ----------------------------

__global__ __launch_bounds__(BDIM, 2)
void gemm32_kernel(const float* __restrict__ A,
                   const float* __restrict__ W,
                   float* __restrict__ C)
{
    extern __shared__ float smem[];
    float* sA  = smem;           // 32*256 = 8192
    float* sWa = smem + 8192;    // 2048
    float* sWb = smem + 10240;   // 2048

    const int tid = threadIdx.x;
    const int tn  = tid >> 5;
    const int f0  = (tid & 31) * 8;
    const int r0  = tn * 4;

    {
        const float* src = A + (size_t)blockIdx.x * 32 * 256;
        #pragma unroll
        for (int u = 0; u < 8; ++u)
            *(float4*)&sA[tid * 4 + u * 1024] = *(const float4*)&src[tid * 4 + u * 1024];
    }
    *(float4*)&sWa[tid * 8]     = *(const float4*)&W[tid * 8];
    *(float4*)&sWa[tid * 8 + 4] = *(const float4*)&W[tid * 8 + 4];
    __syncthreads();

    unsigned long long acc[4][4];
    #pragma unroll
    for (int j = 0; j < 4; ++j)
        #pragma unroll
        for (int i = 0; i < 4; ++i) acc[j][i] = 0ull;

    #pragma unroll 1
    for (int k0 = 0; k0 < 256; k0 += 8) {
        const float* cur = ((k0 >> 3) & 1) ? sWb : sWa;
        float*       nxt = ((k0 >> 3) & 1) ? sWa : sWb;
        float4 p0, p1;
        const bool more = (k0 + 8) < 256;
        if (more) {
            p0 = *(const float4*)&W[(k0 + 8) * 256 + tid * 8];
            p1 = *(const float4*)&W[(k0 + 8) * 256 + tid * 8 + 4];
        }
        mma_tile8<4>(cur, sA + k0, 256, r0, f0, acc);
        if (more) {
            *(float4*)&nxt[tid * 8]     = p0;
            *(float4*)&nxt[tid * 8 + 4] = p1;
        }
        __syncthreads();
    }

    #pragma unroll
    for (int j = 0; j < 4; ++j) {
        float w[8];
        #pragma unroll
        for (int i2 = 0; i2 < 4; ++i2) {
            float2 v = unpack2(acc[j][i2]);
            w[2*i2] = v.x; w[2*i2+1] = v.y;
        }
        const int row = blockIdx.x * 32 + r0 + j;
        *(float4*)&C[(size_t)row * 256 + f0]     = make_float4(w[0], w[1], w[2], w[3]);
        *(float4*)&C[(size_t)row * 256 + f0 + 4] = make_float4(w[4], w[5], w[6], w[7]);
    }
}

// ---- K2: fused filter MLP + gather + aggregate, 1 CTA per atom -------------
// smem (floats): sF[0,8192) f_ij tile; during GEMM2 its first 4096 floats are
// W2 double buffers and [4096,6144) the reduce buffer.  sH[8192,24576): H;
// its first 4096 floats double as W1 buffers during GEMM1.  Then sM, sR.

__global__ __launch_bounds__(BDIM, 2)
void fused_filter_kernel(const float* __restrict__ f_ij,
                         const float* __restrict__ r_ij,
                         const float* __restrict__ nmask,
                         const int*   __restrict__ neigh,
                         const float* __restrict__ W1,
                         const float* __restrict__ b1,
                         const float* __restrict__ W2,
                         const float* __restrict__ b2,
                         const float* __restrict__ XF,
                         float* __restrict__ Y)
{
    extern __shared__ float smem[];
    float* sF   = smem;
    float* sH   = smem + 8192;
    float* sW1a = sH;                 // aliases sH rows 0..7
    float* sW1b = sH + 2048;          // aliases sH rows 8..15
    float* sW2a = sF;                 // aliases sF (dead during GEMM2)
    float* sW2b = sF + 2048;
    float* sRed = sF + 4096;          // 2048 floats
    float* sM   = smem + 24576;       // 64
    int*   sR   = (int*)(smem + 24640); // 64

    const int atom = blockIdx.x;
    const int tid  = threadIdx.x;
    const int tn   = tid >> 5;
    const int f0   = (tid & 31) * 8;
    const int n0   = tn * 8;

    // stage f_ij tile [64,128], masks, neighbor rows
    {
        const float* src = f_ij + (size_t)atom * (NB * KS);
        #pragma unroll
        for (int u = 0; u < 8; ++u)
            *(float4*)&sF[tid * 4 + u * 1024] = *(const float4*)&src[tid * 4 + u * 1024];
    }
    if (tid < NB) {
        float r = r_ij[atom * NB + tid];
        float m = nmask[atom * NB + tid];
        sM[tid] = (r <= CUTOFF) ? m : 0.0f;
        sR[tid] = (atom >> 9) * 512 + neigh[atom * NB + tid];
    }
    // stage W1 tile 0
    *(float4*)&sW1a[tid * 8]     = *(const float4*)&W1[tid * 8];
    *(float4*)&sW1a[tid * 8 + 4] = *(const float4*)&W1[tid * 8 + 4];
    __syncthreads();

    unsigned long long acc[8][4];
    #pragma unroll
    for (int j = 0; j < 8; ++j)
        #pragma unroll
        for (int i = 0; i < 4; ++i) acc[j][i] = 0ull;

    // ---- GEMM1: P = F @ W1 ----
    #pragma unroll 1
    for (int k0 = 0; k0 < KS; k0 += 8) {
        const float* cur = ((k0 >> 3) & 1) ? sW1b : sW1a;
        float*       nxt = ((k0 >> 3) & 1) ? sW1a : sW1b;
        float4 p0, p1;
        const bool more = (k0 + 8) < KS;
        if (more) {
            p0 = *(const float4*)&W1[(k0 + 8) * 256 + tid * 8];
            p1 = *(const float4*)&W1[(k0 + 8) * 256 + tid * 8 + 4];
        }
        mma_tile8<8>(cur, sF + k0, KS, n0, f0, acc);
        if (more) {
            *(float4*)&nxt[tid * 8]     = p0;
            *(float4*)&nxt[tid * 8 + 4] = p1;
        }
        __syncthreads();
    }

    // epilogue: H = ssp(P + b1) into sH (W1 buffers dead after final sync)
    {
        float4 ba  = *(const float4*)&b1[f0];
        float4 bb4 = *(const float4*)&b1[f0 + 4];
        float bb[8] = {ba.x, ba.y, ba.z, ba.w, bb4.x, bb4.y, bb4.z, bb4.w};
        #pragma unroll
        for (int j = 0; j < 8; ++j) {
            float h[8];
            #pragma unroll
            for (int i2 = 0; i2 < 4; ++i2) {
                float2 v = unpack2(acc[j][i2]);
                h[2*i2]   = sspf(v.x + bb[2*i2]);
                h[2*i2+1] = sspf(v.y + bb[2*i2+1]);
            }
            *(float4*)&sH[(n0 + j) * NF + f0]     = make_float4(h[0], h[1], h[2], h[3]);
            *(float4*)&sH[(n0 + j) * NF + f0 + 4] = make_float4(h[4], h[5], h[6], h[7]);
        }
    }
    __syncthreads();
    // stage W2 tile 0 into sF-region buffers (sF dead now)
    *(float4*)&sW2a[tid * 8]     = *(const float4*)&W2[tid * 8];
    *(float4*)&sW2a[tid * 8 + 4] = *(const float4*)&W2[tid * 8 + 4];

    #pragma unroll
    for (int j = 0; j < 8; ++j)
        #pragma unroll
        for (int i = 0; i < 4; ++i) acc[j][i] = 0ull;
    __syncthreads();

    // ---- GEMM2: Wf = H @ W2 ----
    #pragma unroll 1
    for (int k0 = 0; k0 < NF; k0 += 8) {
        const float* cur = ((k0 >> 3) & 1) ? sW2b : sW2a;
        float*       nxt = ((k0 >> 3) & 1) ? sW2a : sW2b;
        float4 p0, p1;
        const bool more = (k0 + 8) < NF;
        if (more) {
            p0 = *(const float4*)&W2[(k0 + 8) * 256 + tid * 8];
            p1 = *(const float4*)&W2[(k0 + 8) * 256 + tid * 8 + 4];
        }
        mma_tile8<8>(cur, sH + k0, NF, n0, f0, acc);
        if (more) {
            *(float4*)&nxt[tid * 8]     = p0;
            *(float4*)&nxt[tid * 8 + 4] = p1;
        }
        __syncthreads();
    }

    // epilogue: partial y += m * (Wf + b2) * XF[neighbor]
    float part[8];
    #pragma unroll
    for (int i = 0; i < 8; ++i) part[i] = 0.0f;
    {
        float4 ba  = *(const float4*)&b2[f0];
        float4 bb4 = *(const float4*)&b2[f0 + 4];
        float bb[8] = {ba.x, ba.y, ba.z, ba.w, bb4.x, bb4.y, bb4.z, bb4.w};
        #pragma unroll
        for (int j = 0; j < 8; ++j) {
            const int n = n0 + j;
            const float m = sM[n];              // warp-uniform
            if (m != 0.0f) {
                const float* xr = XF + (size_t)sR[n] * NF + f0;
                float4 xa = *(const float4*)xr;
                float4 xb = *(const float4*)(xr + 4);
                float xv[8] = {xa.x, xa.y, xa.z, xa.w, xb.x, xb.y, xb.z, xb.w};
                #pragma unroll
                for (int i2 = 0; i2 < 4; ++i2) {
                    float2 v = unpack2(acc[j][i2]);
                    part[2*i2]   = fmaf(m * (v.x + bb[2*i2]),   xv[2*i2],   part[2*i2]);
                    part[2*i2+1] = fmaf(m * (v.y + bb[2*i2+1]), xv[2*i2+1], part[2*i2+1]);
                }
            }
        }
    }
    #pragma unroll
    for (int i = 0; i < 8; ++i)
        sRed[tn * NF + f0 + i] = part[i];
    __syncthreads();
    {
        float y = 0.0f;
        #pragma unroll
        for (int g = 0; g < 8; ++g) y += sRed[g * NF + tid];
        Y[(size_t)atom * NF + tid] = y;
    }
}

// ---- K3: fused tail: out = ssp((Y@Wf2o + bf2o)@Wd + G@Wang + bd) -----------

__global__ __launch_bounds__(BDIM, 2)
void tail_kernel(const float* __restrict__ Yin,
                 const float* __restrict__ Gin,
                 const float* __restrict__ W_f2out,
                 const float* __restrict__ b_f2out,
                 const float* __restrict__ W_dense,
                 const float* __restrict__ b_dense,
                 const float* __restrict__ W_ang,
                 float* __restrict__ out)
{
    extern __shared__ float smem[];
    float* sY  = smem;            // 8192
    float* sT  = smem + 8192;     // 8192
    float* sG  = smem + 16384;    // 4096
    float* sWa = smem + 20480;    // 2048
    float* sWb = smem + 22528;    // 2048

    const int tid = threadIdx.x;
    const int tn  = tid >> 5;
    const int f0  = (tid & 31) * 8;
    const int r0  = tn * 4;

    {
        const float* src = Yin + (size_t)blockIdx.x * 32 * 256;
        #pragma unroll
        for (int u = 0; u < 8; ++u)
            *(float4*)&sY[tid * 4 + u * 1024] = *(const float4*)&src[tid * 4 + u * 1024];
        const float* srcg = Gin + (size_t)blockIdx.x * 32 * 128;
        #pragma unroll
        for (int u = 0; u < 4; ++u)
            *(float4*)&sG[tid * 4 + u * 1024] = *(const float4*)&srcg[tid * 4 + u * 1024];
    }
    *(float4*)&sWa[tid * 8]     = *(const float4*)&W_f2out[tid * 8];
    *(float4*)&sWa[tid * 8 + 4] = *(const float4*)&W_f2out[tid * 8 + 4];
    __syncthreads();

    unsigned long long acc[4][4];
    #pragma unroll
    for (int j = 0; j < 4; ++j)
        #pragma unroll
        for (int i = 0; i < 4; ++i) acc[j][i] = 0ull;

    // phase 1: T = Y @ W_f2out + b_f2out
    #pragma unroll 1
    for (int k0 = 0; k0 < 256; k0 += 8) {
        const float* cur = ((k0 >> 3) & 1) ? sWb : sWa;
        float*       nxt = ((k0 >> 3) & 1) ? sWa : sWb;
        float4 p0, p1;
        const bool more = (k0 + 8) < 256;
        if (more) {
            p0 = *(const float4*)&W_f2out[(k0 + 8) * 256 + tid * 8];
            p1 = *(const float4*)&W_f2out[(k0 + 8) * 256 + tid * 8 + 4];
        }
        mma_tile8<4>(cur, sY + k0, 256, r0, f0, acc);
        if (more) {
            *(float4*)&nxt[tid * 8]     = p0;
            *(float4*)&nxt[tid * 8 + 4] = p1;
        }
        __syncthreads();
    }
    {
        float4 ba  = *(const float4*)&b_f2out[f0];
        float4 bb4 = *(const float4*)&b_f2out[f0 + 4];
        float bb[8] = {ba.x, ba.y, ba.z, ba.w, bb4.x, bb4.y, bb4.z, bb4.w};
        #pragma unroll
        for (int j = 0; j < 4; ++j) {
            float w[8];
            #pragma unroll
            for (int i2 = 0; i2 < 4; ++i2) {
                float2 v = unpack2(acc[j][i2]);
                w[2*i2] = v.x + bb[2*i2]; w[2*i2+1] = v.y + bb[2*i2+1];
            }
            *(float4*)&sT[(r0 + j) * 256 + f0]     = make_float4(w[0], w[1], w[2], w[3]);
            *(float4*)&sT[(r0 + j) * 256 + f0 + 4] = make_float4(w[4], w[5], w[6], w[7]);
        }
    }
    __syncthreads();
    *(float4*)&sWa[tid * 8]     = *(const float4*)&W_dense[tid * 8];
    *(float4*)&sWa[tid * 8 + 4] = *(const float4*)&W_dense[tid * 8 + 4];
    #pragma unroll
    for (int j = 0; j < 4; ++j)
        #pragma unroll
        for (int i = 0; i < 4; ++i) acc[j][i] = 0ull;
    __syncthreads();

    // phase 2a: U = T @ W_dense
    #pragma unroll 1
    for (int k0 = 0; k0 < 256; k0 += 8) {
        const float* cur = ((k0 >> 3) & 1) ? sWb : sWa;
        float*       nxt = ((k0 >> 3) & 1) ? sWa : sWb;
        float4 p0, p1;
        const bool more = (k0 + 8) < 256;
        if (more) {
            p0 = *(const float4*)&W_dense[(k0 + 8) * 256 + tid * 8];
            p1 = *(const float4*)&W_dense[(k0 + 8) * 256 + tid * 8 + 4];
        } else {  // prefetch first W_ang tile instead
            p0 = *(const float4*)&W_ang[tid * 8];
            p1 = *(const float4*)&W_ang[tid * 8 + 4];
        }
        mma_tile8<4>(cur, sT + k0, 256, r0, f0, acc);
        *(float4*)&nxt[tid * 8]     = p0;
        *(float4*)&nxt[tid * 8 + 4] = p1;
        __syncthreads();
    }
    // phase 2b: U += G @ W_ang  (K=128)
    #pragma unroll 1
    for (int k0 = 0; k0 < 128; k0 += 8) {
        const float* cur = ((k0 >> 3) & 1) ? sWb : sWa;
        float*       nxt = ((k0 >> 3) & 1) ? sWa : sWb;
        float4 p0, p1;
        const bool more = (k0 + 8) < 128;
        if (more) {
            p0 = *(const float4*)&W_ang[(k0 + 8) * 256 + tid * 8];
            p1 = *(const float4*)&W_ang[(k0 + 8) * 256 + tid * 8 + 4];
        }
        mma_tile8<4>(cur, sG + k0, 128, r0, f0, acc);
        if (more) {
            *(float4*)&nxt[tid * 8]     = p0;
            *(float4*)&nxt[tid * 8 + 4] = p1;
        }
        __syncthreads();
    }

    {
        float4 ba  = *(const float4*)&b_dense[f0];
        float4 bb4 = *(const float4*)&b_dense[f0 + 4];
        float bb[8] = {ba.x, ba.y, ba.z, ba.w, bb4.x, bb4.y, bb4.z, bb4.w};
        #pragma unroll
        for (int j = 0; j < 4; ++j) {
            float w[8];
            #pragma unroll
            for (int i2 = 0; i2 < 4; ++i2) {
                float2 v = unpack2(acc[j][i2]);
                w[2*i2]   = sspf(v.x + bb[2*i2]);
                w[2*i2+1] = sspf(v.y + bb[2*i2+1]);
            }
            const int row = blockIdx.x * 32 + r0 + j;
            *(float4*)&out[(size_t)row * 256 + f0]     = make_float4(w[0], w[1], w[2], w[3]);
            *(float4*)&out[(size_t)row * 256 + f0 + 4] = make_float4(w[4], w[5], w[6], w[7]);
        }
    }
}

// ---------------------------------------------------------------------------

extern "C" void kernel_launch(void* const* d_in, const int* in_sizes, int n_in,
                              void* d_out, int out_size)
{
    const float* x        = (const float*)d_in[0];
    const float* r_ij     = (const float*)d_in[1];
    const float* f_ij     = (const float*)d_in[2];
    const float* G_i      = (const float*)d_in[3];
    const float* nmask    = (const float*)d_in[4];
    const int*   neigh    = (const int*)  d_in[5];
    const float* W_in2f   = (const float*)d_in[6];
    const float* W1       = (const float*)d_in[7];
    const float* b1       = (const float*)d_in[8];
    const float* W2       = (const float*)d_in[9];
    const float* b2       = (const float*)d_in[10];
    const float* W_f2out  = (const float*)d_in[11];
    const float* b_f2out  = (const float*)d_in[12];
    const float* W_dense  = (const float*)d_in[13];
    const float* b_dense  = (const float*)d_in[14];
    const float* W_ang    = (const float*)d_in[15];
    float* out = (float*)d_out;

    float *pXF, *pY;
    cudaGetSymbolAddress((void**)&pXF, g_XF);
    cudaGetSymbolAddress((void**)&pY,  g_Y);

    const size_t smem1 = (8192 + 4096) * 4;       // 49,152
    const size_t smem2 = (24576 + 128) * 4;       // 98,816
    const size_t smem3 = (24576) * 4;             // 98,304

    cudaFuncSetAttribute(gemm32_kernel,
                         cudaFuncAttributeMaxDynamicSharedMemorySize, (int)smem1);
    cudaFuncSetAttribute(fused_filter_kernel,
                         cudaFuncAttributeMaxDynamicSharedMemorySize, (int)smem2);
    cudaFuncSetAttribute(tail_kernel,
                         cudaFuncAttributeMaxDynamicSharedMemorySize, (int)smem3);

    gemm32_kernel<<<NATOMS / 32, BDIM, smem1>>>(x, W_in2f, pXF);
    fused_filter_kernel<<<NATOMS, BDIM, smem2>>>(
        f_ij, r_ij, nmask, neigh, W1, b1, W2, b2, pXF, pY);
    tail_kernel<<<NATOMS / 32, BDIM, smem3>>>(
        pY, G_i, W_f2out, b_f2out, W_dense, b_dense, W_ang, out);
}

// round 6
// speedup vs baseline: 1.3964x; 1.3964x over previous
#include <cuda_runtime.h>
#include <cuda_bf16.h>
#include <cstdint>

// ---------------------------------------------------------------------------
// SchNet interaction block, sm_103 — v6: mma.sync (HMMA) bf16-split K2.
//   prep:  W1^T, W2^T -> bf16 hi/lo                (prep_w)
//   K1:    XF = x @ W_in2f                         (gemm32, FFMA2)
//   K2:    fused filter MLP + gather + aggregate   (k2_hmma, mma.sync bf16)
//   K3:    ssp((Y@Wf2o+b)@Wd + G@Wang + b)         (tail, FFMA2)
// K2 GEMMs: D += Ahi*Bhi + Ahi*Blo + Alo*Bhi (bf16 splits, fp32 acc)
// -> ~1e-5 relative error. No tcgen05 (ptxas target is plain sm_103).
// ---------------------------------------------------------------------------

#define BDIM 256
#define NATOMS 4096
#define CUTOFF 5.0f

// K2 smem layout (bytes)
#define SXS        260                 // sX row stride in floats
#define SMEM_B_OFF 66560               // after sX: 64*260*4
#define BUF_BYTES  24576               // one double-buffer slot (hi+lo)
#define LO_OFF     12288               // lo split offset inside a slot
#define SMEM_M_OFF 115712
#define SMEM_R_OFF 115968
#define SMEM_RED_OFF 116224
#define SMEM_K2_TOTAL 118272

__device__ float g_XF[NATOMS * 256];
__device__ float g_Y [NATOMS * 256];
__device__ __align__(16) __nv_bfloat16 g_w1h[256 * 128];
__device__ __align__(16) __nv_bfloat16 g_w1l[256 * 128];
__device__ __align__(16) __nv_bfloat16 g_w2h[256 * 256];
__device__ __align__(16) __nv_bfloat16 g_w2l[256 * 256];

// ================= helpers =================

__device__ __forceinline__ uint32_t smem_u32(const void* p) {
    uint32_t a;
    asm("{ .reg .u64 t; cvta.to.shared.u64 t, %1; cvt.u32.u64 %0, t; }" : "=r"(a) : "l"(p));
    return a;
}
__device__ __forceinline__ float sspf(float v) {
    float e = __expf(v);
    float r = __logf(fmaf(0.5f, e, 0.5f));
    return (v > 60.0f) ? (v - 0.69314718055994531f) : r;
}
__device__ __forceinline__ void fma2(unsigned long long& d, unsigned long long a, unsigned long long b) {
    asm("fma.rn.f32x2 %0, %1, %2, %3;" : "=l"(d) : "l"(a), "l"(b), "l"(d));
}
__device__ __forceinline__ unsigned long long pack_dup(float v) {
    unsigned long long r; asm("mov.b64 %0, {%1, %1};" : "=l"(r) : "f"(v)); return r;
}
__device__ __forceinline__ float2 unpack2(unsigned long long u) {
    float2 r; asm("mov.b64 {%0, %1}, %2;" : "=f"(r.x), "=f"(r.y) : "l"(u)); return r;
}
__device__ __forceinline__ float f4c(const float4& v, int i) {
    return i == 0 ? v.x : i == 1 ? v.y : i == 2 ? v.z : v.w;
}
// pack (v0,v1) -> bf16x2, v0 in LOW half
__device__ __forceinline__ uint32_t pack_bf2(float v0, float v1) {
    uint32_t r;
    asm("cvt.rn.satfinite.bf16x2.f32 %0, %1, %2;" : "=r"(r) : "f"(v1), "f"(v0));
    return r;
}
__device__ __forceinline__ float bf2_lo(uint32_t p) { return __uint_as_float(p << 16); }
__device__ __forceinline__ float bf2_hi(uint32_t p) { return __uint_as_float(p & 0xffff0000u); }

__device__ __forceinline__ void mma_bf16(float* d, uint32_t a0, uint32_t a1, uint32_t a2, uint32_t a3,
                                         uint32_t b0, uint32_t b1) {
    asm volatile("mma.sync.aligned.m16n8k16.row.col.f32.bf16.bf16.f32 "
                 "{%0,%1,%2,%3}, {%4,%5,%6,%7}, {%8,%9}, {%0,%1,%2,%3};"
                 : "+f"(d[0]), "+f"(d[1]), "+f"(d[2]), "+f"(d[3])
                 : "r"(a0), "r"(a1), "r"(a2), "r"(a3), "r"(b0), "r"(b1));
}

__device__ __forceinline__ void cp16(uint32_t dst, const void* src) {
    asm volatile("cp.async.cg.shared.global [%0], [%1], 16;" :: "r"(dst), "l"(src) : "memory");
}
#define CP_COMMIT() asm volatile("cp.async.commit_group;" ::: "memory")
#define CP_WAIT0()  asm volatile("cp.async.wait_group 0;" ::: "memory")

// stage one [256 f][16 k] chunk (hi+lo) of a prepped weight into buf slot.
// dst row stride = 12 words (48B). thread tid handles f = tid.
__device__ __forceinline__ void stage_w(uint32_t sbase, int buf,
                                        const __nv_bfloat16* wh, const __nv_bfloat16* wl,
                                        int rowlen, int s, int tid) {
    uint32_t d = sbase + SMEM_B_OFF + (uint32_t)buf * BUF_BYTES + (uint32_t)tid * 48;
    const char* gh = (const char*)(wh + tid * rowlen + s * 16);
    const char* gl = (const char*)(wl + tid * rowlen + s * 16);
    cp16(d,           gh);
    cp16(d + 16,      gh + 16);
    cp16(d + LO_OFF,      gl);
    cp16(d + LO_OFF + 16, gl + 16);
}

// one K=16 step: acc[2 mtiles][8 ntiles][4] += A(sX) * B(staged chunk)
__device__ __forceinline__ void gemm_kstep(float (&acc)[2][8][4], const float* sX, int k0,
                                           const uint32_t* WH, int mt, int nb, int q, int c) {
    uint32_t ah[2][4], al[2][4];
    #pragma unroll
    for (int t = 0; t < 2; ++t) {
        const float* bp = sX + (mt * 32 + t * 16 + q) * SXS + k0 + 2 * c;
        float2 v0 = *(const float2*)(bp);
        float2 v1 = *(const float2*)(bp + 8 * SXS);
        float2 v2 = *(const float2*)(bp + 8);
        float2 v3 = *(const float2*)(bp + 8 * SXS + 8);
        ah[t][0] = pack_bf2(v0.x, v0.y); al[t][0] = pack_bf2(v0.x - bf2_lo(ah[t][0]), v0.y - bf2_hi(ah[t][0]));
        ah[t][1] = pack_bf2(v1.x, v1.y); al[t][1] = pack_bf2(v1.x - bf2_lo(ah[t][1]), v1.y - bf2_hi(ah[t][1]));
        ah[t][2] = pack_bf2(v2.x, v2.y); al[t][2] = pack_bf2(v2.x - bf2_lo(ah[t][2]), v2.y - bf2_hi(ah[t][2]));
        ah[t][3] = pack_bf2(v3.x, v3.y); al[t][3] = pack_bf2(v3.x - bf2_lo(ah[t][3]), v3.y - bf2_hi(ah[t][3]));
    }
    const uint32_t* WL = WH + (LO_OFF / 4);
    #pragma unroll
    for (int nt = 0; nt < 8; ++nt) {
        const int f = nb * 64 + nt * 8 + q;
        uint32_t bh0 = WH[f * 12 + c], bh1 = WH[f * 12 + c + 4];
        uint32_t bl0 = WL[f * 12 + c], bl1 = WL[f * 12 + c + 4];
        mma_bf16(acc[0][nt], ah[0][0], ah[0][1], ah[0][2], ah[0][3], bh0, bh1);
        mma_bf16(acc[0][nt], ah[0][0], ah[0][1], ah[0][2], ah[0][3], bl0, bl1);
        mma_bf16(acc[0][nt], al[0][0], al[0][1], al[0][2], al[0][3], bh0, bh1);
        mma_bf16(acc[1][nt], ah[1][0], ah[1][1], ah[1][2], ah[1][3], bh0, bh1);
        mma_bf16(acc[1][nt], ah[1][0], ah[1][1], ah[1][2], ah[1][3], bl0, bl1);
        mma_bf16(acc[1][nt], al[1][0], al[1][1], al[1][2], al[1][3], bh0, bh1);
    }
}

// ================= prep: W1^T, W2^T -> bf16 hi/lo =================

__global__ void prep_w(const float* __restrict__ W1, const float* __restrict__ W2,
                       __nv_bfloat16* __restrict__ w1h, __nv_bfloat16* __restrict__ w1l,
                       __nv_bfloat16* __restrict__ w2h, __nv_bfloat16* __restrict__ w2l)
{
    int i = blockIdx.x * 256 + threadIdx.x;
    if (i < 32768) {                       // W1T[n][k] <- W1[k][n], [256][128]
        int n = i >> 7, k = i & 127;
        float v = W1[k * 256 + n];
        __nv_bfloat16 h = __float2bfloat16(v);
        w1h[i] = h; w1l[i] = __float2bfloat16(v - __bfloat162float(h));
    } else {                               // W2T[n][k] <- W2[k][n], [256][256]
        int i2 = i - 32768;
        int n = i2 >> 8, k = i2 & 255;
        float v = W2[k * 256 + n];
        __nv_bfloat16 h = __float2bfloat16(v);
        w2h[i2] = h; w2l[i2] = __float2bfloat16(v - __bfloat162float(h));
    }
}

// ================= K2: HMMA fused filter (1 CTA = 1 atom) =================

__global__ __launch_bounds__(BDIM)
void k2_hmma(const float* __restrict__ f_ij, const float* __restrict__ r_ij,
             const float* __restrict__ nmask, const int* __restrict__ neigh,
             const __nv_bfloat16* __restrict__ w1h, const __nv_bfloat16* __restrict__ w1l,
             const __nv_bfloat16* __restrict__ w2h, const __nv_bfloat16* __restrict__ w2l,
             const float* __restrict__ b1, const float* __restrict__ b2,
             const float* __restrict__ XF, float* __restrict__ Y)
{
    extern __shared__ char smc[];
    float* sX   = (float*)smc;
    float* sM   = (float*)(smc + SMEM_M_OFF);
    int*   sRow = (int*)  (smc + SMEM_R_OFF);
    float* sRed = (float*)(smc + SMEM_RED_OFF);
    const uint32_t sbase = smem_u32(smc);
    const int tid = threadIdx.x, wid = tid >> 5, lane = tid & 31;
    const int q = lane >> 2, c = lane & 3;
    const int mt = wid & 1, nb = wid >> 1;
    const int bid = blockIdx.x;

    // kick off W1 chunk 0 immediately
    stage_w(sbase, 0, w1h, w1l, 128, 0, tid);
    CP_COMMIT();

    // F [64][128] fp32 -> sX (stride SXS)
    {
        const float4* f4 = (const float4*)(f_ij + (size_t)bid * 8192);
        #pragma unroll
        for (int u = 0; u < 8; ++u) {
            int i4 = tid + u * 256;
            int row = i4 >> 5, c4 = i4 & 31;
            *(float4*)(sX + row * SXS + c4 * 4) = f4[i4];
        }
    }
    if (tid < 64) {
        float r = r_ij[bid * 64 + tid];
        float m = nmask[bid * 64 + tid];
        sM[tid]   = (r <= CUTOFF) ? m : 0.0f;
        sRow[tid] = (bid >> 9) * 512 + neigh[bid * 64 + tid];
    }

    float acc[2][8][4];
    #pragma unroll
    for (int a = 0; a < 2; ++a)
        #pragma unroll
        for (int n = 0; n < 8; ++n)
            #pragma unroll
            for (int i = 0; i < 4; ++i) acc[a][n][i] = 0.0f;

    // ---- GEMM1: P = F @ W1 (K=128, 8 ksteps) ----
    #pragma unroll 1
    for (int s = 0; s < 8; ++s) {
        CP_WAIT0();
        __syncthreads();
        if (s < 7) { stage_w(sbase, (s + 1) & 1, w1h, w1l, 128, s + 1, tid); CP_COMMIT(); }
        gemm_kstep(acc, sX, s * 16, (const uint32_t*)(smc + SMEM_B_OFF + (s & 1) * BUF_BYTES),
                   mt, nb, q, c);
    }
    __syncthreads();   // all warps done reading F region

    // kick off W2 chunk 0 while doing the H epilogue
    stage_w(sbase, 0, w2h, w2l, 256, 0, tid);
    CP_COMMIT();

    // ---- H = ssp(P + b1) -> sX cols 0..255 ----
    #pragma unroll
    for (int nt = 0; nt < 8; ++nt) {
        const int col = nb * 64 + nt * 8 + 2 * c;
        float2 bv = *(const float2*)(b1 + col);
        #pragma unroll
        for (int t = 0; t < 2; ++t) {
            const int r0 = mt * 32 + t * 16 + q;
            *(float2*)(sX + r0 * SXS + col) =
                make_float2(sspf(acc[t][nt][0] + bv.x), sspf(acc[t][nt][1] + bv.y));
            *(float2*)(sX + (r0 + 8) * SXS + col) =
                make_float2(sspf(acc[t][nt][2] + bv.x), sspf(acc[t][nt][3] + bv.y));
        }
    }
    #pragma unroll
    for (int a = 0; a < 2; ++a)
        #pragma unroll
        for (int n = 0; n < 8; ++n)
            #pragma unroll
            for (int i = 0; i < 4; ++i) acc[a][n][i] = 0.0f;

    // ---- GEMM2: Wf = H @ W2 (K=256, 16 ksteps) ----
    #pragma unroll 1
    for (int s = 0; s < 16; ++s) {
        CP_WAIT0();
        __syncthreads();
        if (s < 15) { stage_w(sbase, (s + 1) & 1, w2h, w2l, 256, s + 1, tid); CP_COMMIT(); }
        gemm_kstep(acc, sX, s * 16, (const uint32_t*)(smc + SMEM_B_OFF + (s & 1) * BUF_BYTES),
                   mt, nb, q, c);
    }
    __syncthreads();   // all warps done reading H region

    // ---- gather XF rows into sX (coalesced) ----
    #pragma unroll
    for (int rr = 0; rr < 8; ++rr) {
        const int row = wid * 8 + rr;
        const float4* src = (const float4*)(XF + (size_t)sRow[row] * 256);
        *(float4*)(sX + row * SXS + lane * 4)        = src[lane];
        *(float4*)(sX + row * SXS + (lane + 32) * 4) = src[lane + 32];
    }
    __syncthreads();

    // ---- epilogue: y[col] = sum_rows m*(Wf + b2)*xf ----
    #pragma unroll
    for (int nt = 0; nt < 8; ++nt) {
        const int col = nb * 64 + nt * 8 + 2 * c;
        float2 bv = *(const float2*)(b2 + col);
        float pe = 0.0f, po = 0.0f;
        #pragma unroll
        for (int t = 0; t < 2; ++t) {
            #pragma unroll
            for (int p = 0; p < 2; ++p) {
                const int row = mt * 32 + t * 16 + q + 8 * p;
                const float m = sM[row];
                float2 x = *(const float2*)(sX + row * SXS + col);
                pe = fmaf(m * (acc[t][nt][2 * p]     + bv.x), x.x, pe);
                po = fmaf(m * (acc[t][nt][2 * p + 1] + bv.y), x.y, po);
            }
        }
        pe += __shfl_xor_sync(0xffffffffu, pe, 4);
        pe += __shfl_xor_sync(0xffffffffu, pe, 8);
        pe += __shfl_xor_sync(0xffffffffu, pe, 16);
        po += __shfl_xor_sync(0xffffffffu, po, 4);
        po += __shfl_xor_sync(0xffffffffu, po, 8);
        po += __shfl_xor_sync(0xffffffffu, po, 16);
        if (q == nt) {
            sRed[mt * 256 + col]     = pe;
            sRed[mt * 256 + col + 1] = po;
        }
    }
    __syncthreads();
    Y[(size_t)bid * 256 + tid] = sRed[tid] + sRed[256 + tid];
}

// ================= K1 (FFMA2 gemm32) =================

template<int JROWS>
__device__ __forceinline__ void mma_tile8(const float* cur, const float* sA,
                                          int lda, int rowbase, int f0,
                                          unsigned long long (&acc)[JROWS][4])
{
    #pragma unroll
    for (int kq = 0; kq < 8; kq += 4) {
        float4 av[JROWS];
        #pragma unroll
        for (int j = 0; j < JROWS; ++j)
            av[j] = *(const float4*)&sA[(rowbase + j) * lda + kq];
        #pragma unroll
        for (int kk = 0; kk < 4; ++kk) {
            ulonglong2 bva = *(const ulonglong2*)&cur[(kq + kk) * 256 + f0];
            ulonglong2 bvb = *(const ulonglong2*)&cur[(kq + kk) * 256 + f0 + 4];
            #pragma unroll
            for (int j = 0; j < JROWS; ++j) {
                unsigned long long a2 = pack_dup(f4c(av[j], kk));
                fma2(acc[j][0], a2, bva.x);
                fma2(acc[j][1], a2, bva.y);
                fma2(acc[j][2], a2, bvb.x);
                fma2(acc[j][3], a2, bvb.y);
            }
        }
    }
}

__global__ __launch_bounds__(BDIM, 2)
void gemm32_kernel(const float* __restrict__ A, const float* __restrict__ W,
                   float* __restrict__ C)
{
    extern __shared__ float smem[];
    float* sA = smem; float* sWa = smem + 8192; float* sWb = smem + 10240;
    const int tid = threadIdx.x, tn = tid >> 5;
    const int f0 = (tid & 31) * 8, r0 = tn * 4;
    {
        const float* src = A + (size_t)blockIdx.x * 8192;
        #pragma unroll
        for (int u = 0; u < 8; ++u)
            *(float4*)&sA[tid * 4 + u * 1024] = *(const float4*)&src[tid * 4 + u * 1024];
    }
    *(float4*)&sWa[tid * 8]     = *(const float4*)&W[tid * 8];
    *(float4*)&sWa[tid * 8 + 4] = *(const float4*)&W[tid * 8 + 4];
    __syncthreads();
    unsigned long long acc[4][4];
    #pragma unroll
    for (int j = 0; j < 4; ++j) { acc[j][0]=acc[j][1]=acc[j][2]=acc[j][3]=0ull; }
    #pragma unroll 1
    for (int k0 = 0; k0 < 256; k0 += 8) {
        const float* cur = ((k0 >> 3) & 1) ? sWb : sWa;
        float*       nxt = ((k0 >> 3) & 1) ? sWa : sWb;
        float4 p0, p1;
        const bool more = (k0 + 8) < 256;
        if (more) {
            p0 = *(const float4*)&W[(k0 + 8) * 256 + tid * 8];
            p1 = *(const float4*)&W[(k0 + 8) * 256 + tid * 8 + 4];
        }
        mma_tile8<4>(cur, sA + k0, 256, r0, f0, acc);
        if (more) { *(float4*)&nxt[tid * 8] = p0; *(float4*)&nxt[tid * 8 + 4] = p1; }
        __syncthreads();
    }
    #pragma unroll
    for (int j = 0; j < 4; ++j) {
        float w[8];
        #pragma unroll
        for (int i2 = 0; i2 < 4; ++i2) {
            float2 v = unpack2(acc[j][i2]); w[2*i2] = v.x; w[2*i2+1] = v.y;
        }
        const int row = blockIdx.x * 32 + r0 + j;
        *(float4*)&C[(size_t)row * 256 + f0]     = make_float4(w[0], w[1], w[2], w[3]);
        *(float4*)&C[(size_t)row * 256 + f0 + 4] = make_float4(w[4], w[5], w[6], w[7]);
    }
}

// ================= K3 (FFMA2 fused tail) =================

__global__ __launch_bounds__(BDIM, 2)
void tail_kernel(const float* __restrict__ Yin, const float* __restrict__ Gin,
                 const float* __restrict__ W_f2out, const float* __restrict__ b_f2out,
                 const float* __restrict__ W_dense, const float* __restrict__ b_dense,
                 const float* __restrict__ W_ang, float* __restrict__ out)
{
    extern __shared__ float smem[];
    float* sY = smem; float* sT = smem + 8192; float* sG = smem + 16384;
    float* sWa = smem + 20480; float* sWb = smem + 22528;
    const int tid = threadIdx.x, tn = tid >> 5;
    const int f0 = (tid & 31) * 8, r0 = tn * 4;
    {
        const float* src = Yin + (size_t)blockIdx.x * 8192;
        #pragma unroll
        for (int u = 0; u < 8; ++u)
            *(float4*)&sY[tid * 4 + u * 1024] = *(const float4*)&src[tid * 4 + u * 1024];
        const float* srcg = Gin + (size_t)blockIdx.x * 4096;
        #pragma unroll
        for (int u = 0; u < 4; ++u)
            *(float4*)&sG[tid * 4 + u * 1024] = *(const float4*)&srcg[tid * 4 + u * 1024];
    }
    *(float4*)&sWa[tid * 8]     = *(const float4*)&W_f2out[tid * 8];
    *(float4*)&sWa[tid * 8 + 4] = *(const float4*)&W_f2out[tid * 8 + 4];
    __syncthreads();
    unsigned long long acc[4][4];
    #pragma unroll
    for (int j = 0; j < 4; ++j) { acc[j][0]=acc[j][1]=acc[j][2]=acc[j][3]=0ull; }
    #pragma unroll 1
    for (int k0 = 0; k0 < 256; k0 += 8) {
        const float* cur = ((k0 >> 3) & 1) ? sWb : sWa;
        float*       nxt = ((k0 >> 3) & 1) ? sWa : sWb;
        float4 p0, p1;
        const bool more = (k0 + 8) < 256;
        if (more) {
            p0 = *(const float4*)&W_f2out[(k0 + 8) * 256 + tid * 8];
            p1 = *(const float4*)&W_f2out[(k0 + 8) * 256 + tid * 8 + 4];
        }
        mma_tile8<4>(cur, sY + k0, 256, r0, f0, acc);
        if (more) { *(float4*)&nxt[tid * 8] = p0; *(float4*)&nxt[tid * 8 + 4] = p1; }
        __syncthreads();
    }
    {
        float4 ba = *(const float4*)&b_f2out[f0];
        float4 bb4 = *(const float4*)&b_f2out[f0 + 4];
        float bb[8] = {ba.x, ba.y, ba.z, ba.w, bb4.x, bb4.y, bb4.z, bb4.w};
        #pragma unroll
        for (int j = 0; j < 4; ++j) {
            float w[8];
            #pragma unroll
            for (int i2 = 0; i2 < 4; ++i2) {
                float2 v = unpack2(acc[j][i2]);
                w[2*i2] = v.x + bb[2*i2]; w[2*i2+1] = v.y + bb[2*i2+1];
            }
            *(float4*)&sT[(r0 + j) * 256 + f0]     = make_float4(w[0], w[1], w[2], w[3]);
            *(float4*)&sT[(r0 + j) * 256 + f0 + 4] = make_float4(w[4], w[5], w[6], w[7]);
        }
    }
    __syncthreads();
    *(float4*)&sWa[tid * 8]     = *(const float4*)&W_dense[tid * 8];
    *(float4*)&sWa[tid * 8 + 4] = *(const float4*)&W_dense[tid * 8 + 4];
    #pragma unroll
    for (int j = 0; j < 4; ++j) { acc[j][0]=acc[j][1]=acc[j][2]=acc[j][3]=0ull; }
    __syncthreads();
    #pragma unroll 1
    for (int k0 = 0; k0 < 256; k0 += 8) {
        const float* cur = ((k0 >> 3) & 1) ? sWb : sWa;
        float*       nxt = ((k0 >> 3) & 1) ? sWa : sWb;
        float4 p0, p1;
        const bool more = (k0 + 8) < 256;
        if (more) {
            p0 = *(const float4*)&W_dense[(k0 + 8) * 256 + tid * 8];
            p1 = *(const float4*)&W_dense[(k0 + 8) * 256 + tid * 8 + 4];
        } else {
            p0 = *(const float4*)&W_ang[tid * 8];
            p1 = *(const float4*)&W_ang[tid * 8 + 4];
        }
        mma_tile8<4>(cur, sT + k0, 256, r0, f0, acc);
        *(float4*)&nxt[tid * 8] = p0; *(float4*)&nxt[tid * 8 + 4] = p1;
        __syncthreads();
    }
    #pragma unroll 1
    for (int k0 = 0; k0 < 128; k0 += 8) {
        const float* cur = ((k0 >> 3) & 1) ? sWb : sWa;
        float*       nxt = ((k0 >> 3) & 1) ? sWa : sWb;
        float4 p0, p1;
        const bool more = (k0 + 8) < 128;
        if (more) {
            p0 = *(const float4*)&W_ang[(k0 + 8) * 256 + tid * 8];
            p1 = *(const float4*)&W_ang[(k0 + 8) * 256 + tid * 8 + 4];
        }
        mma_tile8<4>(cur, sG + k0, 128, r0, f0, acc);
        if (more) { *(float4*)&nxt[tid * 8] = p0; *(float4*)&nxt[tid * 8 + 4] = p1; }
        __syncthreads();
    }
    {
        float4 ba = *(const float4*)&b_dense[f0];
        float4 bb4 = *(const float4*)&b_dense[f0 + 4];
        float bb[8] = {ba.x, ba.y, ba.z, ba.w, bb4.x, bb4.y, bb4.z, bb4.w};
        #pragma unroll
        for (int j = 0; j < 4; ++j) {
            float w[8];
            #pragma unroll
            for (int i2 = 0; i2 < 4; ++i2) {
                float2 v = unpack2(acc[j][i2]);
                w[2*i2] = sspf(v.x + bb[2*i2]); w[2*i2+1] = sspf(v.y + bb[2*i2+1]);
            }
            const int row = blockIdx.x * 32 + r0 + j;
            *(float4*)&out[(size_t)row * 256 + f0]     = make_float4(w[0], w[1], w[2], w[3]);
            *(float4*)&out[(size_t)row * 256 + f0 + 4] = make_float4(w[4], w[5], w[6], w[7]);
        }
    }
}

// ---------------------------------------------------------------------------

extern "C" void kernel_launch(void* const* d_in, const int* in_sizes, int n_in,
                              void* d_out, int out_size)
{
    const float* x        = (const float*)d_in[0];
    const float* r_ij     = (const float*)d_in[1];
    const float* f_ij     = (const float*)d_in[2];
    const float* G_i      = (const float*)d_in[3];
    const float* nmask    = (const float*)d_in[4];
    const int*   neigh    = (const int*)  d_in[5];
    const float* W_in2f   = (const float*)d_in[6];
    const float* W1       = (const float*)d_in[7];
    const float* b1       = (const float*)d_in[8];
    const float* W2       = (const float*)d_in[9];
    const float* b2       = (const float*)d_in[10];
    const float* W_f2out  = (const float*)d_in[11];
    const float* b_f2out  = (const float*)d_in[12];
    const float* W_dense  = (const float*)d_in[13];
    const float* b_dense  = (const float*)d_in[14];
    const float* W_ang    = (const float*)d_in[15];
    float* out = (float*)d_out;

    float *pXF, *pY;
    __nv_bfloat16 *p1h, *p1l, *p2h, *p2l;
    cudaGetSymbolAddress((void**)&pXF, g_XF);
    cudaGetSymbolAddress((void**)&pY,  g_Y);
    cudaGetSymbolAddress((void**)&p1h, g_w1h);
    cudaGetSymbolAddress((void**)&p1l, g_w1l);
    cudaGetSymbolAddress((void**)&p2h, g_w2h);
    cudaGetSymbolAddress((void**)&p2l, g_w2l);

    const size_t smem1 = (8192 + 4096) * 4;
    const size_t smem2 = SMEM_K2_TOTAL;
    const size_t smem3 = 24576 * 4;

    cudaFuncSetAttribute(gemm32_kernel, cudaFuncAttributeMaxDynamicSharedMemorySize, (int)smem1);
    cudaFuncSetAttribute(k2_hmma,       cudaFuncAttributeMaxDynamicSharedMemorySize, (int)smem2);
    cudaFuncSetAttribute(tail_kernel,   cudaFuncAttributeMaxDynamicSharedMemorySize, (int)smem3);

    prep_w<<<384, 256>>>(W1, W2, p1h, p1l, p2h, p2l);
    gemm32_kernel<<<NATOMS / 32, BDIM, smem1>>>(x, W_in2f, pXF);
    k2_hmma<<<NATOMS, BDIM, smem2>>>(
        f_ij, r_ij, nmask, neigh, p1h, p1l, p2h, p2l, b1, b2, pXF, pY);
    tail_kernel<<<NATOMS / 32, BDIM, smem3>>>(
        pY, G_i, W_f2out, b_f2out, W_dense, b_dense, W_ang, out);
}

// round 7
// speedup vs baseline: 2.4711x; 1.7696x over previous
#include <cuda_runtime.h>
#include <cuda_bf16.h>
#include <cstdint>

// ---------------------------------------------------------------------------
// SchNet interaction block, sm_103 — v7: HMMA K2 with conflict-free B path.
//   prep:  W1^T, W2^T -> pre-swizzled bf16 hi/lo chunk images (prep_w)
//   K1:    XF = x @ W_in2f                         (gemm32, FFMA2)
//   K2:    fused filter MLP + gather + aggregate   (k2_hmma, mma.sync bf16)
//   K3:    ssp((Y@Wf2o+b)@Wd + G@Wang + b)         (tail, FFMA2)
// K2 GEMMs: D += Ahi*Bhi + Ahi*Blo + Alo*Bhi (bf16 splits, fp32 acc).
// v7: B fragments come from one LDS.128 per ntile, bank-conflict-free via
// per-row slot rotation baked into the prepped global layout.
// ---------------------------------------------------------------------------

#define BDIM 256
#define NATOMS 4096
#define CUTOFF 5.0f

// K2 smem layout (bytes)
#define SXS        260                 // sX row stride in floats
#define SLOT_OFF   66560               // after sX: 64*260*4
#define BUF_BYTES  16384               // one staged chunk (256 f x 64B)
#define SMEM_M_OFF 99328
#define SMEM_R_OFF 99584
#define SMEM_RED_OFF 99840
#define SMEM_K2_TOTAL 101888

__device__ float g_XF[NATOMS * 256];
__device__ float g_Y [NATOMS * 256];
__device__ __align__(16) uint4 g_w1s[8 * 1024];    // 8 chunks x 256 f x 4 slots
__device__ __align__(16) uint4 g_w2s[16 * 1024];   // 16 chunks

// ================= helpers =================

__device__ __forceinline__ uint32_t smem_u32(const void* p) {
    uint32_t a;
    asm("{ .reg .u64 t; cvta.to.shared.u64 t, %1; cvt.u32.u64 %0, t; }" : "=r"(a) : "l"(p));
    return a;
}
__device__ __forceinline__ float sspf(float v) {
    float e = __expf(v);
    float r = __logf(fmaf(0.5f, e, 0.5f));
    return (v > 60.0f) ? (v - 0.69314718055994531f) : r;
}
__device__ __forceinline__ void fma2(unsigned long long& d, unsigned long long a, unsigned long long b) {
    asm("fma.rn.f32x2 %0, %1, %2, %3;" : "=l"(d) : "l"(a), "l"(b), "l"(d));
}
__device__ __forceinline__ unsigned long long pack_dup(float v) {
    unsigned long long r; asm("mov.b64 %0, {%1, %1};" : "=l"(r) : "f"(v)); return r;
}
__device__ __forceinline__ float2 unpack2(unsigned long long u) {
    float2 r; asm("mov.b64 {%0, %1}, %2;" : "=f"(r.x), "=f"(r.y) : "l"(u)); return r;
}
__device__ __forceinline__ float f4c(const float4& v, int i) {
    return i == 0 ? v.x : i == 1 ? v.y : i == 2 ? v.z : v.w;
}
// pack (v0,v1) -> bf16x2, v0 in LOW half
__device__ __forceinline__ uint32_t pack_bf2(float v0, float v1) {
    uint32_t r;
    asm("cvt.rn.satfinite.bf16x2.f32 %0, %1, %2;" : "=r"(r) : "f"(v1), "f"(v0));
    return r;
}
__device__ __forceinline__ float bf2_lo(uint32_t p) { return __uint_as_float(p << 16); }
__device__ __forceinline__ float bf2_hi(uint32_t p) { return __uint_as_float(p & 0xffff0000u); }

__device__ __forceinline__ void mma_bf16(float* d, uint32_t a0, uint32_t a1, uint32_t a2, uint32_t a3,
                                         uint32_t b0, uint32_t b1) {
    asm volatile("mma.sync.aligned.m16n8k16.row.col.f32.bf16.bf16.f32 "
                 "{%0,%1,%2,%3}, {%4,%5,%6,%7}, {%8,%9}, {%0,%1,%2,%3};"
                 : "+f"(d[0]), "+f"(d[1]), "+f"(d[2]), "+f"(d[3])
                 : "r"(a0), "r"(a1), "r"(a2), "r"(a3), "r"(b0), "r"(b1));
}

__device__ __forceinline__ void cp16(uint32_t dst, const void* src) {
    asm volatile("cp.async.cg.shared.global [%0], [%1], 16;" :: "r"(dst), "l"(src) : "memory");
}
#define CP_COMMIT() asm volatile("cp.async.commit_group;" ::: "memory")
#define CP_WAIT0()  asm volatile("cp.async.wait_group 0;" ::: "memory")

// stage one pre-swizzled 16KB chunk image into a smem slot (coalesced)
__device__ __forceinline__ void stage_w(uint32_t sbase, int buf, const uint4* ws, int s, int tid) {
    uint32_t d = sbase + SLOT_OFF + (uint32_t)buf * BUF_BYTES + (uint32_t)tid * 64;
    const char* g = (const char*)(ws + s * 1024) + tid * 64;
    cp16(d,      g);
    cp16(d + 16, g + 16);
    cp16(d + 32, g + 32);
    cp16(d + 48, g + 48);
}

// one K=16 step: acc[2 mtiles][8 ntiles][4] += A(sX fp32, split live) * B(slot)
__device__ __forceinline__ void gemm_kstep(float (&acc)[2][8][4], const float* sX, int k0,
                                           const char* slot, int mt, int nb, int q, int c,
                                           int slSel) {
    uint32_t ah[2][4], al[2][4];
    #pragma unroll
    for (int t = 0; t < 2; ++t) {
        const float* bp = sX + (mt * 32 + t * 16 + q) * SXS + k0 + 2 * c;
        float2 v0 = *(const float2*)(bp);
        float2 v1 = *(const float2*)(bp + 8 * SXS);
        float2 v2 = *(const float2*)(bp + 8);
        float2 v3 = *(const float2*)(bp + 8 * SXS + 8);
        ah[t][0] = pack_bf2(v0.x, v0.y); al[t][0] = pack_bf2(v0.x - bf2_lo(ah[t][0]), v0.y - bf2_hi(ah[t][0]));
        ah[t][1] = pack_bf2(v1.x, v1.y); al[t][1] = pack_bf2(v1.x - bf2_lo(ah[t][1]), v1.y - bf2_hi(ah[t][1]));
        ah[t][2] = pack_bf2(v2.x, v2.y); al[t][2] = pack_bf2(v2.x - bf2_lo(ah[t][2]), v2.y - bf2_hi(ah[t][2]));
        ah[t][3] = pack_bf2(v3.x, v3.y); al[t][3] = pack_bf2(v3.x - bf2_lo(ah[t][3]), v3.y - bf2_hi(ah[t][3]));
    }
    #pragma unroll
    for (int nt = 0; nt < 8; ++nt) {
        const int f = nb * 64 + nt * 8 + q;
        uint4 B = *(const uint4*)(slot + f * 64 + slSel * 16);
        mma_bf16(acc[0][nt], ah[0][0], ah[0][1], ah[0][2], ah[0][3], B.x, B.y);
        mma_bf16(acc[0][nt], ah[0][0], ah[0][1], ah[0][2], ah[0][3], B.z, B.w);
        mma_bf16(acc[0][nt], al[0][0], al[0][1], al[0][2], al[0][3], B.x, B.y);
        mma_bf16(acc[1][nt], ah[1][0], ah[1][1], ah[1][2], ah[1][3], B.x, B.y);
        mma_bf16(acc[1][nt], ah[1][0], ah[1][1], ah[1][2], ah[1][3], B.z, B.w);
        mma_bf16(acc[1][nt], al[1][0], al[1][1], al[1][2], al[1][3], B.x, B.y);
    }
}

// ================= prep: pre-swizzled chunk images =================
// Record for (chunk s, row f, slot): slot = (c + (f>>1)) & 3 holds k-pair c:
//   { hi(k0+2c, k0+2c+1), hi(k0+8+2c, +1), lo(...), lo(...) },  k0 = 16*s.

__global__ void prep_w(const float* __restrict__ W1, const float* __restrict__ W2,
                       uint4* __restrict__ w1s, uint4* __restrict__ w2s)
{
    int i = blockIdx.x * 256 + threadIdx.x;   // 24576 total
    const float* W; uint4* dst; int idx;
    if (i < 8192) { W = W1; dst = w1s; idx = i; }
    else          { W = W2; dst = w2s; idx = i - 8192; }
    const int s = idx >> 10;
    const int r = idx & 1023;
    const int f = r >> 2;
    const int slotIdx = r & 3;
    const int c = (slotIdx - (f >> 1)) & 3;
    const int k0 = s * 16 + 2 * c;
    float v0 = W[(size_t)(k0)     * 256 + f];
    float v1 = W[(size_t)(k0 + 1) * 256 + f];
    float v2 = W[(size_t)(k0 + 8) * 256 + f];
    float v3 = W[(size_t)(k0 + 9) * 256 + f];
    uint32_t h0 = pack_bf2(v0, v1);
    uint32_t h1 = pack_bf2(v2, v3);
    uint32_t l0 = pack_bf2(v0 - bf2_lo(h0), v1 - bf2_hi(h0));
    uint32_t l1 = pack_bf2(v2 - bf2_lo(h1), v3 - bf2_hi(h1));
    dst[s * 1024 + f * 4 + slotIdx] = make_uint4(h0, h1, l0, l1);
}

// ================= K2: HMMA fused filter (1 CTA = 1 atom) =================

__global__ __launch_bounds__(BDIM)
void k2_hmma(const float* __restrict__ f_ij, const float* __restrict__ r_ij,
             const float* __restrict__ nmask, const int* __restrict__ neigh,
             const uint4* __restrict__ w1s, const uint4* __restrict__ w2s,
             const float* __restrict__ b1, const float* __restrict__ b2,
             const float* __restrict__ XF, float* __restrict__ Y)
{
    extern __shared__ char smc[];
    float* sX   = (float*)smc;
    float* sM   = (float*)(smc + SMEM_M_OFF);
    int*   sRow = (int*)  (smc + SMEM_R_OFF);
    float* sRed = (float*)(smc + SMEM_RED_OFF);
    const uint32_t sbase = smem_u32(smc);
    const int tid = threadIdx.x, wid = tid >> 5, lane = tid & 31;
    const int q = lane >> 2, c = lane & 3;
    const int slSel = (c + (q >> 1)) & 3;
    const int mt = wid & 1, nb = wid >> 1;
    const int bid = blockIdx.x;

    // kick off W1 chunk 0 immediately
    stage_w(sbase, 0, w1s, 0, tid);
    CP_COMMIT();

    // F [64][128] fp32 -> sX (stride SXS)
    {
        const float4* f4 = (const float4*)(f_ij + (size_t)bid * 8192);
        #pragma unroll
        for (int u = 0; u < 8; ++u) {
            int i4 = tid + u * 256;
            int row = i4 >> 5, c4 = i4 & 31;
            *(float4*)(sX + row * SXS + c4 * 4) = f4[i4];
        }
    }
    if (tid < 64) {
        float r = r_ij[bid * 64 + tid];
        float m = nmask[bid * 64 + tid];
        sM[tid]   = (r <= CUTOFF) ? m : 0.0f;
        sRow[tid] = (bid >> 9) * 512 + neigh[bid * 64 + tid];
    }

    float acc[2][8][4];
    #pragma unroll
    for (int a = 0; a < 2; ++a)
        #pragma unroll
        for (int n = 0; n < 8; ++n)
            #pragma unroll
            for (int i = 0; i < 4; ++i) acc[a][n][i] = 0.0f;

    // ---- GEMM1: P = F @ W1 (K=128, 8 ksteps) ----
    #pragma unroll 1
    for (int s = 0; s < 8; ++s) {
        CP_WAIT0();
        __syncthreads();
        if (s < 7) { stage_w(sbase, (s + 1) & 1, w1s, s + 1, tid); CP_COMMIT(); }
        gemm_kstep(acc, sX, s * 16, smc + SLOT_OFF + (s & 1) * BUF_BYTES, mt, nb, q, c, slSel);
    }
    __syncthreads();   // all warps done reading F region

    // kick off W2 chunk 0 while doing the H epilogue
    stage_w(sbase, 0, w2s, 0, tid);
    CP_COMMIT();

    // ---- H = ssp(P + b1) -> sX cols 0..255 ----
    #pragma unroll
    for (int nt = 0; nt < 8; ++nt) {
        const int col = nb * 64 + nt * 8 + 2 * c;
        float2 bv = *(const float2*)(b1 + col);
        #pragma unroll
        for (int t = 0; t < 2; ++t) {
            const int r0 = mt * 32 + t * 16 + q;
            *(float2*)(sX + r0 * SXS + col) =
                make_float2(sspf(acc[t][nt][0] + bv.x), sspf(acc[t][nt][1] + bv.y));
            *(float2*)(sX + (r0 + 8) * SXS + col) =
                make_float2(sspf(acc[t][nt][2] + bv.x), sspf(acc[t][nt][3] + bv.y));
        }
    }
    #pragma unroll
    for (int a = 0; a < 2; ++a)
        #pragma unroll
        for (int n = 0; n < 8; ++n)
            #pragma unroll
            for (int i = 0; i < 4; ++i) acc[a][n][i] = 0.0f;

    // ---- GEMM2: Wf = H @ W2 (K=256, 16 ksteps) ----
    #pragma unroll 1
    for (int s = 0; s < 16; ++s) {
        CP_WAIT0();
        __syncthreads();
        if (s < 15) { stage_w(sbase, (s + 1) & 1, w2s, s + 1, tid); CP_COMMIT(); }
        gemm_kstep(acc, sX, s * 16, smc + SLOT_OFF + (s & 1) * BUF_BYTES, mt, nb, q, c, slSel);
    }
    __syncthreads();   // all warps done reading H region

    // ---- gather XF rows into sX (coalesced) ----
    #pragma unroll
    for (int rr = 0; rr < 8; ++rr) {
        const int row = wid * 8 + rr;
        const float4* src = (const float4*)(XF + (size_t)sRow[row] * 256);
        *(float4*)(sX + row * SXS + lane * 4)        = src[lane];
        *(float4*)(sX + row * SXS + (lane + 32) * 4) = src[lane + 32];
    }
    __syncthreads();

    // ---- epilogue: y[col] = sum_rows m*(Wf + b2)*xf ----
    #pragma unroll
    for (int nt = 0; nt < 8; ++nt) {
        const int col = nb * 64 + nt * 8 + 2 * c;
        float2 bv = *(const float2*)(b2 + col);
        float pe = 0.0f, po = 0.0f;
        #pragma unroll
        for (int t = 0; t < 2; ++t) {
            #pragma unroll
            for (int p = 0; p < 2; ++p) {
                const int row = mt * 32 + t * 16 + q + 8 * p;
                const float m = sM[row];
                float2 x = *(const float2*)(sX + row * SXS + col);
                pe = fmaf(m * (acc[t][nt][2 * p]     + bv.x), x.x, pe);
                po = fmaf(m * (acc[t][nt][2 * p + 1] + bv.y), x.y, po);
            }
        }
        pe += __shfl_xor_sync(0xffffffffu, pe, 4);
        pe += __shfl_xor_sync(0xffffffffu, pe, 8);
        pe += __shfl_xor_sync(0xffffffffu, pe, 16);
        po += __shfl_xor_sync(0xffffffffu, po, 4);
        po += __shfl_xor_sync(0xffffffffu, po, 8);
        po += __shfl_xor_sync(0xffffffffu, po, 16);
        if (q == nt) {
            sRed[mt * 256 + col]     = pe;
            sRed[mt * 256 + col + 1] = po;
        }
    }
    __syncthreads();
    Y[(size_t)bid * 256 + tid] = sRed[tid] + sRed[256 + tid];
}

// ================= K1 (FFMA2 gemm32) =================

template<int JROWS>
__device__ __forceinline__ void mma_tile8(const float* cur, const float* sA,
                                          int lda, int rowbase, int f0,
                                          unsigned long long (&acc)[JROWS][4])
{
    #pragma unroll
    for (int kq = 0; kq < 8; kq += 4) {
        float4 av[JROWS];
        #pragma unroll
        for (int j = 0; j < JROWS; ++j)
            av[j] = *(const float4*)&sA[(rowbase + j) * lda + kq];
        #pragma unroll
        for (int kk = 0; kk < 4; ++kk) {
            ulonglong2 bva = *(const ulonglong2*)&cur[(kq + kk) * 256 + f0];
            ulonglong2 bvb = *(const ulonglong2*)&cur[(kq + kk) * 256 + f0 + 4];
            #pragma unroll
            for (int j = 0; j < JROWS; ++j) {
                unsigned long long a2 = pack_dup(f4c(av[j], kk));
                fma2(acc[j][0], a2, bva.x);
                fma2(acc[j][1], a2, bva.y);
                fma2(acc[j][2], a2, bvb.x);
                fma2(acc[j][3], a2, bvb.y);
            }
        }
    }
}

__global__ __launch_bounds__(BDIM, 2)
void gemm32_kernel(const float* __restrict__ A, const float* __restrict__ W,
                   float* __restrict__ C)
{
    extern __shared__ float smem[];
    float* sA = smem; float* sWa = smem + 8192; float* sWb = smem + 10240;
    const int tid = threadIdx.x, tn = tid >> 5;
    const int f0 = (tid & 31) * 8, r0 = tn * 4;
    {
        const float* src = A + (size_t)blockIdx.x * 8192;
        #pragma unroll
        for (int u = 0; u < 8; ++u)
            *(float4*)&sA[tid * 4 + u * 1024] = *(const float4*)&src[tid * 4 + u * 1024];
    }
    *(float4*)&sWa[tid * 8]     = *(const float4*)&W[tid * 8];
    *(float4*)&sWa[tid * 8 + 4] = *(const float4*)&W[tid * 8 + 4];
    __syncthreads();
    unsigned long long acc[4][4];
    #pragma unroll
    for (int j = 0; j < 4; ++j) { acc[j][0]=acc[j][1]=acc[j][2]=acc[j][3]=0ull; }
    #pragma unroll 1
    for (int k0 = 0; k0 < 256; k0 += 8) {
        const float* cur = ((k0 >> 3) & 1) ? sWb : sWa;
        float*       nxt = ((k0 >> 3) & 1) ? sWa : sWb;
        float4 p0, p1;
        const bool more = (k0 + 8) < 256;
        if (more) {
            p0 = *(const float4*)&W[(k0 + 8) * 256 + tid * 8];
            p1 = *(const float4*)&W[(k0 + 8) * 256 + tid * 8 + 4];
        }
        mma_tile8<4>(cur, sA + k0, 256, r0, f0, acc);
        if (more) { *(float4*)&nxt[tid * 8] = p0; *(float4*)&nxt[tid * 8 + 4] = p1; }
        __syncthreads();
    }
    #pragma unroll
    for (int j = 0; j < 4; ++j) {
        float w[8];
        #pragma unroll
        for (int i2 = 0; i2 < 4; ++i2) {
            float2 v = unpack2(acc[j][i2]); w[2*i2] = v.x; w[2*i2+1] = v.y;
        }
        const int row = blockIdx.x * 32 + r0 + j;
        *(float4*)&C[(size_t)row * 256 + f0]     = make_float4(w[0], w[1], w[2], w[3]);
        *(float4*)&C[(size_t)row * 256 + f0 + 4] = make_float4(w[4], w[5], w[6], w[7]);
    }
}

// ================= K3 (FFMA2 fused tail) =================

__global__ __launch_bounds__(BDIM, 2)
void tail_kernel(const float* __restrict__ Yin, const float* __restrict__ Gin,
                 const float* __restrict__ W_f2out, const float* __restrict__ b_f2out,
                 const float* __restrict__ W_dense, const float* __restrict__ b_dense,
                 const float* __restrict__ W_ang, float* __restrict__ out)
{
    extern __shared__ float smem[];
    float* sY = smem; float* sT = smem + 8192; float* sG = smem + 16384;
    float* sWa = smem + 20480; float* sWb = smem + 22528;
    const int tid = threadIdx.x, tn = tid >> 5;
    const int f0 = (tid & 31) * 8, r0 = tn * 4;
    {
        const float* src = Yin + (size_t)blockIdx.x * 8192;
        #pragma unroll
        for (int u = 0; u < 8; ++u)
            *(float4*)&sY[tid * 4 + u * 1024] = *(const float4*)&src[tid * 4 + u * 1024];
        const float* srcg = Gin + (size_t)blockIdx.x * 4096;
        #pragma unroll
        for (int u = 0; u < 4; ++u)
            *(float4*)&sG[tid * 4 + u * 1024] = *(const float4*)&srcg[tid * 4 + u * 1024];
    }
    *(float4*)&sWa[tid * 8]     = *(const float4*)&W_f2out[tid * 8];
    *(float4*)&sWa[tid * 8 + 4] = *(const float4*)&W_f2out[tid * 8 + 4];
    __syncthreads();
    unsigned long long acc[4][4];
    #pragma unroll
    for (int j = 0; j < 4; ++j) { acc[j][0]=acc[j][1]=acc[j][2]=acc[j][3]=0ull; }
    #pragma unroll 1
    for (int k0 = 0; k0 < 256; k0 += 8) {
        const float* cur = ((k0 >> 3) & 1) ? sWb : sWa;
        float*       nxt = ((k0 >> 3) & 1) ? sWa : sWb;
        float4 p0, p1;
        const bool more = (k0 + 8) < 256;
        if (more) {
            p0 = *(const float4*)&W_f2out[(k0 + 8) * 256 + tid * 8];
            p1 = *(const float4*)&W_f2out[(k0 + 8) * 256 + tid * 8 + 4];
        }
        mma_tile8<4>(cur, sY + k0, 256, r0, f0, acc);
        if (more) { *(float4*)&nxt[tid * 8] = p0; *(float4*)&nxt[tid * 8 + 4] = p1; }
        __syncthreads();
    }
    {
        float4 ba = *(const float4*)&b_f2out[f0];
        float4 bb4 = *(const float4*)&b_f2out[f0 + 4];
        float bb[8] = {ba.x, ba.y, ba.z, ba.w, bb4.x, bb4.y, bb4.z, bb4.w};
        #pragma unroll
        for (int j = 0; j < 4; ++j) {
            float w[8];
            #pragma unroll
            for (int i2 = 0; i2 < 4; ++i2) {
                float2 v = unpack2(acc[j][i2]);
                w[2*i2] = v.x + bb[2*i2]; w[2*i2+1] = v.y + bb[2*i2+1];
            }
            *(float4*)&sT[(r0 + j) * 256 + f0]     = make_float4(w[0], w[1], w[2], w[3]);
            *(float4*)&sT[(r0 + j) * 256 + f0 + 4] = make_float4(w[4], w[5], w[6], w[7]);
        }
    }
    __syncthreads();
    *(float4*)&sWa[tid * 8]     = *(const float4*)&W_dense[tid * 8];
    *(float4*)&sWa[tid * 8 + 4] = *(const float4*)&W_dense[tid * 8 + 4];
    #pragma unroll
    for (int j = 0; j < 4; ++j) { acc[j][0]=acc[j][1]=acc[j][2]=acc[j][3]=0ull; }
    __syncthreads();
    #pragma unroll 1
    for (int k0 = 0; k0 < 256; k0 += 8) {
        const float* cur = ((k0 >> 3) & 1) ? sWb : sWa;
        float*       nxt = ((k0 >> 3) & 1) ? sWa : sWb;
        float4 p0, p1;
        const bool more = (k0 + 8) < 256;
        if (more) {
            p0 = *(const float4*)&W_dense[(k0 + 8) * 256 + tid * 8];
            p1 = *(const float4*)&W_dense[(k0 + 8) * 256 + tid * 8 + 4];
        } else {
            p0 = *(const float4*)&W_ang[tid * 8];
            p1 = *(const float4*)&W_ang[tid * 8 + 4];
        }
        mma_tile8<4>(cur, sT + k0, 256, r0, f0, acc);
        *(float4*)&nxt[tid * 8] = p0; *(float4*)&nxt[tid * 8 + 4] = p1;
        __syncthreads();
    }
    #pragma unroll 1
    for (int k0 = 0; k0 < 128; k0 += 8) {
        const float* cur = ((k0 >> 3) & 1) ? sWb : sWa;
        float*       nxt = ((k0 >> 3) & 1) ? sWa : sWb;
        float4 p0, p1;
        const bool more = (k0 + 8) < 128;
        if (more) {
            p0 = *(const float4*)&W_ang[(k0 + 8) * 256 + tid * 8];
            p1 = *(const float4*)&W_ang[(k0 + 8) * 256 + tid * 8 + 4];
        }
        mma_tile8<4>(cur, sG + k0, 128, r0, f0, acc);
        if (more) { *(float4*)&nxt[tid * 8] = p0; *(float4*)&nxt[tid * 8 + 4] = p1; }
        __syncthreads();
    }
    {
        float4 ba = *(const float4*)&b_dense[f0];
        float4 bb4 = *(const float4*)&b_dense[f0 + 4];
        float bb[8] = {ba.x, ba.y, ba.z, ba.w, bb4.x, bb4.y, bb4.z, bb4.w};
        #pragma unroll
        for (int j = 0; j < 4; ++j) {
            float w[8];
            #pragma unroll
            for (int i2 = 0; i2 < 4; ++i2) {
                float2 v = unpack2(acc[j][i2]);
                w[2*i2] = sspf(v.x + bb[2*i2]); w[2*i2+1] = sspf(v.y + bb[2*i2+1]);
            }
            const int row = blockIdx.x * 32 + r0 + j;
            *(float4*)&out[(size_t)row * 256 + f0]     = make_float4(w[0], w[1], w[2], w[3]);
            *(float4*)&out[(size_t)row * 256 + f0 + 4] = make_float4(w[4], w[5], w[6], w[7]);
        }
    }
}

// ---------------------------------------------------------------------------

extern "C" void kernel_launch(void* const* d_in, const int* in_sizes, int n_in,
                              void* d_out, int out_size)
{
    const float* x        = (const float*)d_in[0];
    const float* r_ij     = (const float*)d_in[1];
    const float* f_ij     = (const float*)d_in[2];
    const float* G_i      = (const float*)d_in[3];
    const float* nmask    = (const float*)d_in[4];
    const int*   neigh    = (const int*)  d_in[5];
    const float* W_in2f   = (const float*)d_in[6];
    const float* W1       = (const float*)d_in[7];
    const float* b1       = (const float*)d_in[8];
    const float* W2       = (const float*)d_in[9];
    const float* b2       = (const float*)d_in[10];
    const float* W_f2out  = (const float*)d_in[11];
    const float* b_f2out  = (const float*)d_in[12];
    const float* W_dense  = (const float*)d_in[13];
    const float* b_dense  = (const float*)d_in[14];
    const float* W_ang    = (const float*)d_in[15];
    float* out = (float*)d_out;

    float *pXF, *pY;
    uint4 *p1s, *p2s;
    cudaGetSymbolAddress((void**)&pXF, g_XF);
    cudaGetSymbolAddress((void**)&pY,  g_Y);
    cudaGetSymbolAddress((void**)&p1s, g_w1s);
    cudaGetSymbolAddress((void**)&p2s, g_w2s);

    const size_t smem1 = (8192 + 4096) * 4;
    const size_t smem2 = SMEM_K2_TOTAL;
    const size_t smem3 = 24576 * 4;

    cudaFuncSetAttribute(gemm32_kernel, cudaFuncAttributeMaxDynamicSharedMemorySize, (int)smem1);
    cudaFuncSetAttribute(k2_hmma,       cudaFuncAttributeMaxDynamicSharedMemorySize, (int)smem2);
    cudaFuncSetAttribute(tail_kernel,   cudaFuncAttributeMaxDynamicSharedMemorySize, (int)smem3);

    prep_w<<<96, 256>>>(W1, W2, p1s, p2s);
    gemm32_kernel<<<NATOMS / 32, BDIM, smem1>>>(x, W_in2f, pXF);
    k2_hmma<<<NATOMS, BDIM, smem2>>>(
        f_ij, r_ij, nmask, neigh, p1s, p2s, b1, b2, pXF, pY);
    tail_kernel<<<NATOMS / 32, BDIM, smem3>>>(
        pY, G_i, W_f2out, b_f2out, W_dense, b_dense, W_ang, out);
}